// round 15
// baseline (speedup 1.0000x reference)
#include <cuda_runtime.h>
#include <cuda_fp16.h>
#include <math.h>
#include <stdint.h>

#define BATCH 2
#define SEQ   2048
#define CH    2048
#define NH    16
#define HD    128
#define WIN   512
#define MROWS (BATCH*SEQ)   // 4096

// attention scale folded with log2(e): 1/sqrt(128) * 1.44269504
#define QSCALE (0.08838834764831845f * 1.4426950408889634f)

// ---------------- scratch (static device globals) ---------------------------
__device__ __half g_Xh[MROWS*CH];
__device__ __half g_Wh[4][CH*CH];         // transposed weights [n][k] fp16
__device__ __half g_Qh[MROWS*CH];         // pre-scaled by QSCALE
__device__ __half g_Kh[MROWS*CH];
__device__ __half g_Vh[MROWS*CH];
__device__ __half g_Ah[MROWS*CH];         // attention output fp16
__device__ float  g_cos[SEQ*64];
__device__ float  g_sin[SEQ*64];

// ---------------- helpers ---------------------------------------------------
__device__ __forceinline__ uint32_t s2u(const void* p) {
    uint32_t a;
    asm("{ .reg .u64 t; cvta.to.shared.u64 t, %1; cvt.u32.u64 %0, t; }"
        : "=r"(a) : "l"(p));
    return a;
}
__device__ __forceinline__ void cpa16(uint32_t dst, const void* src) {
    asm volatile("cp.async.cg.shared.global [%0], [%1], 16;" :: "r"(dst), "l"(src));
}
__device__ __forceinline__ void ldm4(uint32_t* r, uint32_t addr) {
    asm volatile("ldmatrix.sync.aligned.m8n8.x4.shared.b16 {%0,%1,%2,%3}, [%4];"
        : "=r"(r[0]), "=r"(r[1]), "=r"(r[2]), "=r"(r[3]) : "r"(addr));
}
__device__ __forceinline__ void ldm4t(uint32_t* r, uint32_t addr) {
    asm volatile("ldmatrix.sync.aligned.m8n8.x4.trans.shared.b16 {%0,%1,%2,%3}, [%4];"
        : "=r"(r[0]), "=r"(r[1]), "=r"(r[2]), "=r"(r[3]) : "r"(addr));
}
__device__ __forceinline__ void mma16(float* d, const uint32_t* a, const uint32_t* b) {
    asm volatile(
        "mma.sync.aligned.m16n8k16.row.col.f32.f16.f16.f32 "
        "{%0,%1,%2,%3}, {%4,%5,%6,%7}, {%8,%9}, {%0,%1,%2,%3};"
        : "+f"(d[0]), "+f"(d[1]), "+f"(d[2]), "+f"(d[3])
        : "r"(a[0]), "r"(a[1]), "r"(a[2]), "r"(a[3]), "r"(b[0]), "r"(b[1]));
}
__device__ __forceinline__ uint32_t h2pack(float a, float b) {
    __half2 h = __floats2half2_rn(a, b);
    return *(uint32_t*)&h;
}
__device__ __forceinline__ float ex2(float x) {
    float r;
    asm("ex2.approx.f32 %0, %1;" : "=f"(r) : "f"(x));
    return r;
}
__device__ __forceinline__ unsigned long long pk2(float lo, float hi) {
    unsigned long long r;
    asm("mov.b64 %0, {%1, %2};" : "=l"(r) : "f"(lo), "f"(hi));
    return r;
}
__device__ __forceinline__ void upk2(unsigned long long v, float& lo, float& hi) {
    asm("mov.b64 {%0, %1}, %2;" : "=f"(lo), "=f"(hi) : "l"(v));
}
__device__ __forceinline__ unsigned long long mul2p(unsigned long long a,
                                                    unsigned long long b) {
    unsigned long long d;
    asm("mul.rn.f32x2 %0, %1, %2;" : "=l"(d) : "l"(a), "l"(b));
    return d;
}
__device__ __forceinline__ unsigned long long add2p(unsigned long long a,
                                                    unsigned long long b) {
    unsigned long long d;
    asm("add.rn.f32x2 %0, %1, %2;" : "=l"(d) : "l"(a), "l"(b));
    return d;
}

// ---------------- fp16 mma GEMM: BK=128/stage (2x 64-col sub-tiles) ---------
// 256 thr (8 warps, 2x4 grid, warp tile 64x32), 3 stages x 64KB = 192KB smem.
// Stage layout: A0[128x64] A1[128x64] B0[128x64] B1[128x64], each 16KB with
// the verified 128B-row SW128 layout.
#define STG_B 65536
#define GEMM_SMEM (3*STG_B)      // 196608

template<int MODE>
__global__ __launch_bounds__(256, 1) void gemm_h(const __half* __restrict__ Ah,
                                                 const __half* __restrict__ Bh0,
                                                 float* __restrict__ C) {
    extern __shared__ char smem[];
    const int z = MODE ? blockIdx.z : 0;
    const __half* Bh = Bh0 + (size_t)z * CH * CH;
    const uint32_t sb = s2u(smem);
    const int tid  = threadIdx.x;
    const int lane = tid & 31;
    const int wid  = tid >> 5;
    const int wm   = (wid >> 2) * 64;
    const int wn   = (wid & 3) * 32;
    const int row0 = blockIdx.y * 128;
    const int col0 = blockIdx.x * 128;

    float acc[4][4][4];
    #pragma unroll
    for (int i = 0; i < 4; i++)
        #pragma unroll
        for (int j = 0; j < 4; j++)
            #pragma unroll
            for (int r = 0; r < 4; r++) acc[i][j][r] = 0.0f;

    auto load_stage = [&](int slot, int kt) {
        #pragma unroll
        for (int half = 0; half < 2; half++) {
            uint32_t ab = sb + slot * STG_B + half * 16384;
            uint32_t bb = ab + 32768;
            int kh = kt + half * 64;
            #pragma unroll
            for (int i = 0; i < 4; i++) {
                int idx = tid + i * 256;
                int row = idx >> 3, ch = idx & 7;
                uint32_t off = row * 128 + ch * 16;
                uint32_t sw = off ^ ((off >> 3) & 0x70);
                cpa16(ab + sw, Ah + (size_t)(row0 + row) * CH + kh + ch * 8);
                cpa16(bb + sw, Bh + (size_t)(col0 + row) * CH + kh + ch * 8);
            }
        }
    };
    auto compute = [&](int slot) {
        #pragma unroll
        for (int half = 0; half < 2; half++) {
            uint32_t ab = sb + slot * STG_B + half * 16384;
            uint32_t bb = ab + 32768;
            #pragma unroll
            for (int ks = 0; ks < 4; ks++) {
                uint32_t aF[4][4], bF[4][2];
                #pragma unroll
                for (int i = 0; i < 4; i++) {
                    int row = wm + i * 16 + (lane & 15);
                    uint32_t off = row * 128 + ks * 32 + ((lane >> 4) << 4);
                    ldm4(aF[i], ab + (off ^ ((off >> 3) & 0x70)));
                }
                #pragma unroll
                for (int j2 = 0; j2 < 2; j2++) {
                    int row = wn + j2 * 16 + ((lane >> 4) << 3) + (lane & 7);
                    uint32_t off = row * 128 + ks * 32 + (((lane >> 3) & 1) << 4);
                    uint32_t r[4];
                    ldm4(r, bb + (off ^ ((off >> 3) & 0x70)));
                    bF[2 * j2][0] = r[0];  bF[2 * j2][1] = r[1];
                    bF[2 * j2 + 1][0] = r[2];  bF[2 * j2 + 1][1] = r[3];
                }
                #pragma unroll
                for (int i = 0; i < 4; i++)
                    #pragma unroll
                    for (int j = 0; j < 4; j++)
                        mma16(acc[i][j], aF[i], bF[j]);
            }
        }
    };

    load_stage(0, 0);
    asm volatile("cp.async.commit_group;" ::: "memory");
    load_stage(1, 128);
    asm volatile("cp.async.commit_group;" ::: "memory");

    #pragma unroll 1
    for (int it = 0; it < 16; it++) {
        asm volatile("cp.async.wait_group 1;" ::: "memory");
        __syncthreads();
        int jn = it + 2;
        if (jn < 16) load_stage(jn % 3, jn * 128);
        asm volatile("cp.async.commit_group;" ::: "memory");
        compute(it % 3);
    }

    if (MODE == 0) {
        #pragma unroll
        for (int i = 0; i < 4; i++) {
            #pragma unroll
            for (int j = 0; j < 4; j++) {
                int r = row0 + wm + i * 16 + (lane >> 2);
                int c = col0 + wn + j * 8 + 2 * (lane & 3);
                *(float2*)&C[(size_t)r * CH + c] =
                    make_float2(acc[i][j][0], acc[i][j][1]);
                *(float2*)&C[(size_t)(r + 8) * CH + c] =
                    make_float2(acc[i][j][2], acc[i][j][3]);
            }
        }
    } else if (z == 2) {
        #pragma unroll
        for (int i = 0; i < 4; i++) {
            #pragma unroll
            for (int j = 0; j < 4; j++) {
                int r = row0 + wm + i * 16 + (lane >> 2);
                int c = col0 + wn + j * 8 + 2 * (lane & 3);
                uint32_t p0 = h2pack(acc[i][j][0], acc[i][j][1]);
                uint32_t p1 = h2pack(acc[i][j][2], acc[i][j][3]);
                *(uint32_t*)&g_Vh[(size_t)r * CH + c] = p0;
                *(uint32_t*)&g_Vh[(size_t)(r + 8) * CH + c] = p1;
            }
        }
    } else {
        // Q/K: stage to smem, apply RoPE, emit fp16 (Q pre-scaled by QSCALE)
        const int SP = 132;
        float* st = (float*)smem;
        __syncthreads();
        #pragma unroll
        for (int i = 0; i < 4; i++) {
            #pragma unroll
            for (int j = 0; j < 4; j++) {
                int r1 = wm + i * 16 + (lane >> 2);
                int c  = wn + j * 8 + 2 * (lane & 3);
                *(float2*)&st[r1 * SP + c] =
                    make_float2(acc[i][j][0], acc[i][j][1]);
                *(float2*)&st[(r1 + 8) * SP + c] =
                    make_float2(acc[i][j][2], acc[i][j][3]);
            }
        }
        __syncthreads();
        const float sc = (z == 0) ? QSCALE : 1.0f;
        int r = tid >> 1, hf = tid & 1;
        int t = (row0 + r) & (SEQ - 1);
        __half* Out = (z == 0 ? g_Qh : g_Kh) + (size_t)(row0 + r) * CH + col0;
        int db0 = hf * 32;
        #pragma unroll
        for (int q = 0; q < 8; q++) {
            int db = db0 + q * 4;
            float4 c4 = *(const float4*)&g_cos[(t << 6) + db];
            float4 s4 = *(const float4*)&g_sin[(t << 6) + db];
            float4 u1 = *(const float4*)&st[r * SP + db];
            float4 u2 = *(const float4*)&st[r * SP + db + 64];
            uint2 w1, w2;
            w1.x = h2pack(sc * (u1.x * c4.x - u2.x * s4.x),
                          sc * (u1.y * c4.y - u2.y * s4.y));
            w1.y = h2pack(sc * (u1.z * c4.z - u2.z * s4.z),
                          sc * (u1.w * c4.w - u2.w * s4.w));
            w2.x = h2pack(sc * (u1.x * s4.x + u2.x * c4.x),
                          sc * (u1.y * s4.y + u2.y * c4.y));
            w2.y = h2pack(sc * (u1.z * s4.z + u2.z * c4.z),
                          sc * (u1.w * s4.w + u2.w * c4.w));
            *(uint2*)&Out[db]      = w1;
            *(uint2*)&Out[db + 64] = w2;
        }
    }
}

// ---------------- fused prep: convert x, transpose weights, rope tables -----
__global__ __launch_bounds__(256) void prep_all(const float4* __restrict__ x4,
                                                const float* __restrict__ W0,
                                                const float* __restrict__ W1,
                                                const float* __restrict__ W2,
                                                const float* __restrict__ W3) {
    __shared__ float t[32][33];
    int bid = blockIdx.x;
    int tid = threadIdx.x;

    if (bid < 8192) {
        int i = bid * 256 + tid;
        float4 v = x4[i];
        __half2 h0 = __floats2half2_rn(v.x, v.y);
        __half2 h1 = __floats2half2_rn(v.z, v.w);
        uint2 u = make_uint2(*(uint32_t*)&h0, *(uint32_t*)&h1);
        ((uint2*)g_Xh)[i] = u;
    } else if (bid < 24576) {
        int tt = bid - 8192;
        int zz = tt >> 12;             // 0..3
        int rem = tt & 4095;
        int bx = (rem >> 6) * 32;      // k base
        int by = (rem & 63) * 32;      // n base
        const float* W = (zz == 0) ? W0 : (zz == 1) ? W1 : (zz == 2) ? W2 : W3;
        __half* Wt = &g_Wh[zz][0];
        int tx = tid & 31, ty = tid >> 5;
        #pragma unroll
        for (int i = 0; i < 4; i++)
            t[ty + 8 * i][tx] = W[(size_t)(bx + ty + 8 * i) * CH + by + tx];
        __syncthreads();
        int r = tid >> 3;
        int c2 = tid & 7;
        #pragma unroll
        for (int p = 0; p < 2; p++) {
            int cc = c2 + p * 8;
            __half2 h = __floats2half2_rn(t[2 * cc][r], t[2 * cc + 1][r]);
            ((__half2*)(Wt + (size_t)(by + r) * CH + bx))[cc] = h;
        }
    } else {
        int idx = (bid - 24576) * 256 + tid;
        int d = idx & 63;
        int tpos = idx >> 6;
        double inv = exp2(-(double)d * 0.20762050593046014);
        double ang = (double)tpos * inv;
        const double TWO_PI = 6.283185307179586477;
        ang -= floor(ang * (1.0 / TWO_PI)) * TWO_PI;
        float s, c;
        sincosf((float)ang, &s, &c);
        g_cos[idx] = c;
        g_sin[idx] = s;
    }
}

// ---------------- Attention: fp16 mma flash (R14, best measured) ------------
#define ATS 136
#define KV_OFF (64*ATS)
#define STAGE_H (2*64*ATS)
#define ATT_SMEM ((64*ATS + 2*STAGE_H)*2)   // 87040 bytes

__device__ __forceinline__ int next_act(int kb, int q0) {
    do { kb += 64; } while (kb < SEQ && (kb + 63 <= q0) && (kb >= q0 - (WIN - 64)));
    return kb;
}

__global__ __launch_bounds__(128) void attn_mma_kernel() {
    extern __shared__ char smem[];
    const uint32_t sb = s2u(smem);
    const int bh = blockIdx.y;
    const int b = bh >> 4;
    const int h = bh & 15;
    const int q0 = blockIdx.x * 64;
    const int tid = threadIdx.x;
    const int lane = tid & 31;
    const int w = tid >> 5;

    const __half* Qg = g_Qh + ((size_t)(b * SEQ) + q0) * CH + h * HD;

    auto load_kv = [&](int stage, int kb) {
        const __half* Kg = g_Kh + ((size_t)(b * SEQ) + kb) * CH + h * HD;
        const __half* Vg = g_Vh + ((size_t)(b * SEQ) + kb) * CH + h * HD;
        uint32_t kbB = sb + (KV_OFF + stage * STAGE_H) * 2;
        uint32_t vbB = kbB + 64 * ATS * 2;
        #pragma unroll
        for (int i = 0; i < 8; i++) {
            int idx = tid + i * 128;
            int row = idx >> 4, ch = idx & 15;
            uint32_t d = (row * ATS + ch * 8) * 2;
            cpa16(kbB + d, Kg + (size_t)row * CH + ch * 8);
            cpa16(vbB + d, Vg + (size_t)row * CH + ch * 8);
        }
    };

    {
        #pragma unroll
        for (int i = 0; i < 8; i++) {
            int idx = tid + i * 128;
            int row = idx >> 4, ch = idx & 15;
            cpa16(sb + (row * ATS + ch * 8) * 2, Qg + (size_t)row * CH + ch * 8);
        }
    }

    int cur = next_act(-64, q0);
    load_kv(0, cur);
    asm volatile("cp.async.commit_group;" ::: "memory");
    int nxt = next_act(cur, q0);
    if (nxt < SEQ) load_kv(1, nxt);
    asm volatile("cp.async.commit_group;" ::: "memory");
    int nn = (nxt < SEQ) ? next_act(nxt, q0) : SEQ;

    float m0 = -1e30f, m1 = -1e30f;
    float l0p = 0.0f, l1p = 0.0f;
    unsigned long long oacc[16][2];
    #pragma unroll
    for (int t = 0; t < 16; t++) { oacc[t][0] = 0ull; oacc[t][1] = 0ull; }

    int stage = 0;
    #pragma unroll 1
    while (cur < SEQ) {
        asm volatile("cp.async.wait_group 1;" ::: "memory");
        __syncthreads();

        uint32_t kbB = sb + (KV_OFF + stage * STAGE_H) * 2;
        uint32_t vbB = kbB + 64 * ATS * 2;

        float sacc[8][4];
        #pragma unroll
        for (int t = 0; t < 8; t++)
            #pragma unroll
            for (int r = 0; r < 4; r++) sacc[t][r] = 0.0f;

        #pragma unroll
        for (int ks = 0; ks < 8; ks++) {
            uint32_t aF[4];
            {
                int row = 16 * w + (lane & 15);
                uint32_t off = (row * ATS + ks * 16 + 8 * (lane >> 4)) * 2;
                ldm4(aF, sb + off);
            }
            #pragma unroll
            for (int jp = 0; jp < 4; jp++) {
                int row = 16 * jp + ((lane >> 4) << 3) + (lane & 7);
                uint32_t off = (row * ATS + ks * 16 + 8 * ((lane >> 3) & 1)) * 2;
                uint32_t r[4];
                ldm4(r, kbB + off);
                mma16(sacc[2 * jp],     aF, r);
                mma16(sacc[2 * jp + 1], aF, r + 2);
            }
        }

        bool needmask = (cur <= q0 + 63) && (cur + 63 >= q0 - (WIN - 1));
        if (needmask) {
            int i0 = q0 + 16 * w + (lane >> 2);
            int i1 = i0 + 8;
            #pragma unroll
            for (int t = 0; t < 8; t++) {
                int j0 = cur + 8 * t + 2 * (lane & 3);
                #pragma unroll
                for (int e = 0; e < 2; e++) {
                    int j = j0 + e;
                    bool msk0 = (j <= i0) && (j >= i0 - (WIN - 1));
                    bool msk1 = (j <= i1) && (j >= i1 - (WIN - 1));
                    if (msk0) sacc[t][e]     = -1e30f;
                    if (msk1) sacc[t][2 + e] = -1e30f;
                }
            }
        }

        float rmax0 = -1e30f, rmax1 = -1e30f;
        #pragma unroll
        for (int t = 0; t < 8; t++) {
            rmax0 = fmaxf(rmax0, fmaxf(sacc[t][0], sacc[t][1]));
            rmax1 = fmaxf(rmax1, fmaxf(sacc[t][2], sacc[t][3]));
        }
        rmax0 = fmaxf(rmax0, __shfl_xor_sync(0xffffffffu, rmax0, 1));
        rmax0 = fmaxf(rmax0, __shfl_xor_sync(0xffffffffu, rmax0, 2));
        rmax1 = fmaxf(rmax1, __shfl_xor_sync(0xffffffffu, rmax1, 1));
        rmax1 = fmaxf(rmax1, __shfl_xor_sync(0xffffffffu, rmax1, 2));
        float mn0 = fmaxf(m0, rmax0), mn1 = fmaxf(m1, rmax1);
        float cr0 = ex2(m0 - mn0), cr1 = ex2(m1 - mn1);

        unsigned long long ps0p = 0ull, ps1p = 0ull;
        #pragma unroll
        for (int t = 0; t < 8; t++) {
            sacc[t][0] = ex2(sacc[t][0] - mn0);
            sacc[t][1] = ex2(sacc[t][1] - mn0);
            sacc[t][2] = ex2(sacc[t][2] - mn1);
            sacc[t][3] = ex2(sacc[t][3] - mn1);
            ps0p = add2p(ps0p, pk2(sacc[t][0], sacc[t][1]));
            ps1p = add2p(ps1p, pk2(sacc[t][2], sacc[t][3]));
        }
        float pa, pb, ps0, ps1;
        upk2(ps0p, pa, pb);  ps0 = pa + pb;
        upk2(ps1p, pa, pb);  ps1 = pa + pb;

        l0p = l0p * cr0 + ps0;  m0 = mn0;
        l1p = l1p * cr1 + ps1;  m1 = mn1;

        unsigned long long c0p = pk2(cr0, cr0), c1p = pk2(cr1, cr1);
        #pragma unroll
        for (int t = 0; t < 16; t++) {
            oacc[t][0] = mul2p(oacc[t][0], c0p);
            oacc[t][1] = mul2p(oacc[t][1], c1p);
        }

        uint32_t aP[4][4];
        #pragma unroll
        for (int k2 = 0; k2 < 4; k2++) {
            aP[k2][0] = h2pack(sacc[2 * k2][0],     sacc[2 * k2][1]);
            aP[k2][1] = h2pack(sacc[2 * k2][2],     sacc[2 * k2][3]);
            aP[k2][2] = h2pack(sacc[2 * k2 + 1][0], sacc[2 * k2 + 1][1]);
            aP[k2][3] = h2pack(sacc[2 * k2 + 1][2], sacc[2 * k2 + 1][3]);
        }

        #pragma unroll
        for (int k2 = 0; k2 < 4; k2++) {
            #pragma unroll
            for (int dt = 0; dt < 8; dt++) {
                int row = 16 * k2 + ((lane >> 3) & 1) * 8 + (lane & 7);
                uint32_t off = (row * ATS + dt * 16 + ((lane >> 4) << 3)) * 2;
                uint32_t r[4];
                ldm4t(r, vbB + off);
                float d0[4], d1[4];
                upk2(oacc[2 * dt][0],     d0[0], d0[1]);
                upk2(oacc[2 * dt][1],     d0[2], d0[3]);
                upk2(oacc[2 * dt + 1][0], d1[0], d1[1]);
                upk2(oacc[2 * dt + 1][1], d1[2], d1[3]);
                mma16(d0, aP[k2], r);
                mma16(d1, aP[k2], r + 2);
                oacc[2 * dt][0]     = pk2(d0[0], d0[1]);
                oacc[2 * dt][1]     = pk2(d0[2], d0[3]);
                oacc[2 * dt + 1][0] = pk2(d1[0], d1[1]);
                oacc[2 * dt + 1][1] = pk2(d1[2], d1[3]);
            }
        }

        __syncthreads();
        if (nn < SEQ) load_kv(stage, nn);
        asm volatile("cp.async.commit_group;" ::: "memory");
        cur = nxt;  nxt = nn;
        nn = (nn < SEQ) ? next_act(nn, q0) : SEQ;
        stage ^= 1;
    }

    float l0 = l0p, l1 = l1p;
    l0 += __shfl_xor_sync(0xffffffffu, l0, 1);
    l0 += __shfl_xor_sync(0xffffffffu, l0, 2);
    l1 += __shfl_xor_sync(0xffffffffu, l1, 1);
    l1 += __shfl_xor_sync(0xffffffffu, l1, 2);

    float il0 = 1.0f / l0, il1 = 1.0f / l1;
    int r0 = q0 + 16 * w + (lane >> 2);
    __half* Og = g_Ah + (size_t)(b * SEQ) * CH + h * HD;
    #pragma unroll
    for (int t = 0; t < 16; t++) {
        int c = 8 * t + 2 * (lane & 3);
        float a0, a1, a2, a3;
        upk2(oacc[t][0], a0, a1);
        upk2(oacc[t][1], a2, a3);
        __half2 h0 = __floats2half2_rn(a0 * il0, a1 * il0);
        __half2 h1 = __floats2half2_rn(a2 * il1, a3 * il1);
        *(__half2*)&Og[(size_t)r0 * CH + c] = h0;
        *(__half2*)&Og[(size_t)(r0 + 8) * CH + c] = h1;
    }
}

// ---------------- launch ----------------------------------------------------
extern "C" void kernel_launch(void* const* d_in, const int* in_sizes, int n_in,
                              void* d_out, int out_size) {
    const float* x  = (const float*)d_in[0];
    const float* Wq = (const float*)d_in[1];
    const float* Wk = (const float*)d_in[2];
    const float* Wv = (const float*)d_in[3];
    const float* Wo = (const float*)d_in[4];
    float* out = (float*)d_out;

    __half *Xh, *Wh, *Ahp;
    cudaGetSymbolAddress((void**)&Xh, g_Xh);
    cudaGetSymbolAddress((void**)&Wh, g_Wh);
    cudaGetSymbolAddress((void**)&Ahp, g_Ah);
    __half* Wh3 = Wh + 3 * (size_t)CH * CH;

    static bool attr_set = false;
    if (!attr_set) {
        cudaFuncSetAttribute(gemm_h<0>,
                             cudaFuncAttributeMaxDynamicSharedMemorySize,
                             GEMM_SMEM);
        cudaFuncSetAttribute(gemm_h<1>,
                             cudaFuncAttributeMaxDynamicSharedMemorySize,
                             GEMM_SMEM);
        cudaFuncSetAttribute(attn_mma_kernel,
                             cudaFuncAttributeMaxDynamicSharedMemorySize,
                             ATT_SMEM);
        attr_set = true;
    }

    prep_all<<<25088, 256>>>((const float4*)x, Wq, Wk, Wv, Wo);

    dim3 gq(CH / 128, MROWS / 128, 3);
    gemm_h<1><<<gq, 256, GEMM_SMEM>>>(Xh, Wh, nullptr);

    attn_mma_kernel<<<dim3(SEQ / 64, BATCH * NH), 128, ATT_SMEM>>>();

    dim3 gg(CH / 128, MROWS / 128, 1);
    gemm_h<0><<<gg, 256, GEMM_SMEM>>>(Ahp, Wh3, out);
}

// round 16
// speedup vs baseline: 1.0962x; 1.0962x over previous
#include <cuda_runtime.h>
#include <cuda_fp16.h>
#include <math.h>
#include <stdint.h>

#define BATCH 2
#define SEQ   2048
#define CH    2048
#define NH    16
#define HD    128
#define WIN   512
#define MROWS (BATCH*SEQ)   // 4096

// attention scale folded with log2(e): 1/sqrt(128) * 1.44269504
#define QSCALE (0.08838834764831845f * 1.4426950408889634f)

// ---------------- scratch (static device globals) ---------------------------
__device__ __half g_Xh[MROWS*CH];
__device__ __half g_Wh[4][CH*CH];         // transposed weights [n][k] fp16
__device__ __half g_Qh[MROWS*CH];         // pre-scaled by QSCALE
__device__ __half g_Kh[MROWS*CH];
__device__ __half g_Vh[MROWS*CH];
__device__ __half g_Ah[MROWS*CH];         // attention output fp16
__device__ float  g_cos[SEQ*64];
__device__ float  g_sin[SEQ*64];

// ---------------- helpers ---------------------------------------------------
__device__ __forceinline__ uint32_t s2u(const void* p) {
    uint32_t a;
    asm("{ .reg .u64 t; cvta.to.shared.u64 t, %1; cvt.u32.u64 %0, t; }"
        : "=r"(a) : "l"(p));
    return a;
}
__device__ __forceinline__ void cpa16(uint32_t dst, const void* src) {
    asm volatile("cp.async.cg.shared.global [%0], [%1], 16;" :: "r"(dst), "l"(src));
}
__device__ __forceinline__ void ldm4(uint32_t* r, uint32_t addr) {
    asm volatile("ldmatrix.sync.aligned.m8n8.x4.shared.b16 {%0,%1,%2,%3}, [%4];"
        : "=r"(r[0]), "=r"(r[1]), "=r"(r[2]), "=r"(r[3]) : "r"(addr));
}
__device__ __forceinline__ void ldm4t(uint32_t* r, uint32_t addr) {
    asm volatile("ldmatrix.sync.aligned.m8n8.x4.trans.shared.b16 {%0,%1,%2,%3}, [%4];"
        : "=r"(r[0]), "=r"(r[1]), "=r"(r[2]), "=r"(r[3]) : "r"(addr));
}
__device__ __forceinline__ void mma16(float* d, const uint32_t* a, const uint32_t* b) {
    asm volatile(
        "mma.sync.aligned.m16n8k16.row.col.f32.f16.f16.f32 "
        "{%0,%1,%2,%3}, {%4,%5,%6,%7}, {%8,%9}, {%0,%1,%2,%3};"
        : "+f"(d[0]), "+f"(d[1]), "+f"(d[2]), "+f"(d[3])
        : "r"(a[0]), "r"(a[1]), "r"(a[2]), "r"(a[3]), "r"(b[0]), "r"(b[1]));
}
__device__ __forceinline__ uint32_t h2pack(float a, float b) {
    __half2 h = __floats2half2_rn(a, b);
    return *(uint32_t*)&h;
}
__device__ __forceinline__ float ex2(float x) {
    float r;
    asm("ex2.approx.f32 %0, %1;" : "=f"(r) : "f"(x));
    return r;
}
// packed f32x2 helpers (sm_103a double-throughput path)
__device__ __forceinline__ unsigned long long pk2(float lo, float hi) {
    unsigned long long r;
    asm("mov.b64 %0, {%1, %2};" : "=l"(r) : "f"(lo), "f"(hi));
    return r;
}
__device__ __forceinline__ void upk2(unsigned long long v, float& lo, float& hi) {
    asm("mov.b64 {%0, %1}, %2;" : "=f"(lo), "=f"(hi) : "l"(v));
}
__device__ __forceinline__ unsigned long long mul2p(unsigned long long a,
                                                    unsigned long long b) {
    unsigned long long d;
    asm("mul.rn.f32x2 %0, %1, %2;" : "=l"(d) : "l"(a), "l"(b));
    return d;
}
__device__ __forceinline__ unsigned long long add2p(unsigned long long a,
                                                    unsigned long long b) {
    unsigned long long d;
    asm("add.rn.f32x2 %0, %1, %2;" : "=l"(d) : "l"(a), "l"(b));
    return d;
}

// ---------------- fp16 mma GEMM (R8 config: 256 thr, warp tile 64x32) -------
#define NST 3
#define STG_B 32768
#define GEMM_SMEM (NST*STG_B)      // 98304

template<int MODE>
__global__ __launch_bounds__(256, 2) void gemm_h(const __half* __restrict__ Ah,
                                                 const __half* __restrict__ Bh0,
                                                 float* __restrict__ C) {
    extern __shared__ char smem[];
    const int z = MODE ? blockIdx.z : 0;
    const __half* Bh = Bh0 + (size_t)z * CH * CH;
    const uint32_t sb = s2u(smem);
    const int tid  = threadIdx.x;
    const int lane = tid & 31;
    const int wid  = tid >> 5;
    const int wm   = (wid >> 2) * 64;
    const int wn   = (wid & 3) * 32;
    const int row0 = blockIdx.y * 128;
    const int col0 = blockIdx.x * 128;

    float acc[4][4][4];
    #pragma unroll
    for (int i = 0; i < 4; i++)
        #pragma unroll
        for (int j = 0; j < 4; j++)
            #pragma unroll
            for (int r = 0; r < 4; r++) acc[i][j][r] = 0.0f;

    auto load_stage = [&](int slot, int kt) {
        uint32_t ab = sb + slot * STG_B;
        uint32_t bb = ab + 16384;
        #pragma unroll
        for (int i = 0; i < 4; i++) {
            int idx = tid + i * 256;
            int row = idx >> 3, ch = idx & 7;
            uint32_t off = row * 128 + ch * 16;
            uint32_t sw = off ^ ((off >> 3) & 0x70);
            cpa16(ab + sw, Ah + (size_t)(row0 + row) * CH + kt + ch * 8);
            cpa16(bb + sw, Bh + (size_t)(col0 + row) * CH + kt + ch * 8);
        }
    };
    auto compute = [&](int slot) {
        uint32_t ab = sb + slot * STG_B;
        uint32_t bb = ab + 16384;
        #pragma unroll
        for (int ks = 0; ks < 4; ks++) {
            uint32_t aF[4][4], bF[4][2];
            #pragma unroll
            for (int i = 0; i < 4; i++) {
                int row = wm + i * 16 + (lane & 15);
                uint32_t off = row * 128 + ks * 32 + ((lane >> 4) << 4);
                ldm4(aF[i], ab + (off ^ ((off >> 3) & 0x70)));
            }
            #pragma unroll
            for (int j2 = 0; j2 < 2; j2++) {
                int row = wn + j2 * 16 + ((lane >> 4) << 3) + (lane & 7);
                uint32_t off = row * 128 + ks * 32 + (((lane >> 3) & 1) << 4);
                uint32_t r[4];
                ldm4(r, bb + (off ^ ((off >> 3) & 0x70)));
                bF[2 * j2][0] = r[0];  bF[2 * j2][1] = r[1];
                bF[2 * j2 + 1][0] = r[2];  bF[2 * j2 + 1][1] = r[3];
            }
            #pragma unroll
            for (int i = 0; i < 4; i++)
                #pragma unroll
                for (int j = 0; j < 4; j++)
                    mma16(acc[i][j], aF[i], bF[j]);
        }
    };

    load_stage(0, 0);
    asm volatile("cp.async.commit_group;" ::: "memory");
    load_stage(1, 64);
    asm volatile("cp.async.commit_group;" ::: "memory");

    #pragma unroll 1
    for (int it = 0; it < 32; it++) {
        asm volatile("cp.async.wait_group 1;" ::: "memory");
        __syncthreads();
        int jn = it + 2;
        if (jn < 32) load_stage(jn % 3, jn * 64);
        asm volatile("cp.async.commit_group;" ::: "memory");
        compute(it % 3);
    }

    if (MODE == 0) {
        #pragma unroll
        for (int i = 0; i < 4; i++) {
            #pragma unroll
            for (int j = 0; j < 4; j++) {
                int r = row0 + wm + i * 16 + (lane >> 2);
                int c = col0 + wn + j * 8 + 2 * (lane & 3);
                *(float2*)&C[(size_t)r * CH + c] =
                    make_float2(acc[i][j][0], acc[i][j][1]);
                *(float2*)&C[(size_t)(r + 8) * CH + c] =
                    make_float2(acc[i][j][2], acc[i][j][3]);
            }
        }
    } else if (z == 2) {
        #pragma unroll
        for (int i = 0; i < 4; i++) {
            #pragma unroll
            for (int j = 0; j < 4; j++) {
                int r = row0 + wm + i * 16 + (lane >> 2);
                int c = col0 + wn + j * 8 + 2 * (lane & 3);
                uint32_t p0 = h2pack(acc[i][j][0], acc[i][j][1]);
                uint32_t p1 = h2pack(acc[i][j][2], acc[i][j][3]);
                *(uint32_t*)&g_Vh[(size_t)r * CH + c] = p0;
                *(uint32_t*)&g_Vh[(size_t)(r + 8) * CH + c] = p1;
            }
        }
    } else {
        // Q/K: stage to smem, apply RoPE, emit fp16 (Q pre-scaled by QSCALE)
        const int SP = 132;
        float* st = (float*)smem;
        __syncthreads();
        #pragma unroll
        for (int i = 0; i < 4; i++) {
            #pragma unroll
            for (int j = 0; j < 4; j++) {
                int r1 = wm + i * 16 + (lane >> 2);
                int c  = wn + j * 8 + 2 * (lane & 3);
                *(float2*)&st[r1 * SP + c] =
                    make_float2(acc[i][j][0], acc[i][j][1]);
                *(float2*)&st[(r1 + 8) * SP + c] =
                    make_float2(acc[i][j][2], acc[i][j][3]);
            }
        }
        __syncthreads();
        const float sc = (z == 0) ? QSCALE : 1.0f;
        int r = tid >> 1, hf = tid & 1;
        int t = (row0 + r) & (SEQ - 1);
        __half* Out = (z == 0 ? g_Qh : g_Kh) + (size_t)(row0 + r) * CH + col0;
        int db0 = hf * 32;
        #pragma unroll
        for (int q = 0; q < 8; q++) {
            int db = db0 + q * 4;
            float4 c4 = *(const float4*)&g_cos[(t << 6) + db];
            float4 s4 = *(const float4*)&g_sin[(t << 6) + db];
            float4 u1 = *(const float4*)&st[r * SP + db];
            float4 u2 = *(const float4*)&st[r * SP + db + 64];
            uint2 w1, w2;
            w1.x = h2pack(sc * (u1.x * c4.x - u2.x * s4.x),
                          sc * (u1.y * c4.y - u2.y * s4.y));
            w1.y = h2pack(sc * (u1.z * c4.z - u2.z * s4.z),
                          sc * (u1.w * c4.w - u2.w * s4.w));
            w2.x = h2pack(sc * (u1.x * s4.x + u2.x * c4.x),
                          sc * (u1.y * s4.y + u2.y * c4.y));
            w2.y = h2pack(sc * (u1.z * s4.z + u2.z * c4.z),
                          sc * (u1.w * s4.w + u2.w * c4.w));
            *(uint2*)&Out[db]      = w1;
            *(uint2*)&Out[db + 64] = w2;
        }
    }
}

// ---------------- fused prep: convert x, transpose weights, rope tables -----
__global__ __launch_bounds__(256) void prep_all(const float4* __restrict__ x4,
                                                const float* __restrict__ W0,
                                                const float* __restrict__ W1,
                                                const float* __restrict__ W2,
                                                const float* __restrict__ W3) {
    __shared__ float t[32][33];
    int bid = blockIdx.x;
    int tid = threadIdx.x;

    if (bid < 8192) {
        int i = bid * 256 + tid;
        float4 v = x4[i];
        __half2 h0 = __floats2half2_rn(v.x, v.y);
        __half2 h1 = __floats2half2_rn(v.z, v.w);
        uint2 u = make_uint2(*(uint32_t*)&h0, *(uint32_t*)&h1);
        ((uint2*)g_Xh)[i] = u;
    } else if (bid < 24576) {
        int tt = bid - 8192;
        int zz = tt >> 12;             // 0..3
        int rem = tt & 4095;
        int bx = (rem >> 6) * 32;      // k base
        int by = (rem & 63) * 32;      // n base
        const float* W = (zz == 0) ? W0 : (zz == 1) ? W1 : (zz == 2) ? W2 : W3;
        __half* Wt = &g_Wh[zz][0];
        int tx = tid & 31, ty = tid >> 5;
        #pragma unroll
        for (int i = 0; i < 4; i++)
            t[ty + 8 * i][tx] = W[(size_t)(bx + ty + 8 * i) * CH + by + tx];
        __syncthreads();
        int r = tid >> 3;
        int c2 = tid & 7;
        #pragma unroll
        for (int p = 0; p < 2; p++) {
            int cc = c2 + p * 8;
            __half2 h = __floats2half2_rn(t[2 * cc][r], t[2 * cc + 1][r]);
            ((__half2*)(Wt + (size_t)(by + r) * CH + bx))[cc] = h;
        }
    } else {
        int idx = (bid - 24576) * 256 + tid;
        int d = idx & 63;
        int tpos = idx >> 6;
        double inv = exp2(-(double)d * 0.20762050593046014);
        double ang = (double)tpos * inv;
        const double TWO_PI = 6.283185307179586477;
        ang -= floor(ang * (1.0 / TWO_PI)) * TWO_PI;
        float s, c;
        sincosf((float)ang, &s, &c);
        g_cos[idx] = c;
        g_sin[idx] = s;
    }
}

// ---------------- Attention: fp16 mma flash, packed-f32x2 softmax -----------
#define ATS 136
#define KV_OFF (64*ATS)
#define STAGE_H (2*64*ATS)
#define ATT_SMEM ((64*ATS + 2*STAGE_H)*2)   // 87040 bytes

__device__ __forceinline__ int next_act(int kb, int q0) {
    do { kb += 64; } while (kb < SEQ && (kb + 63 <= q0) && (kb >= q0 - (WIN - 64)));
    return kb;
}

__global__ __launch_bounds__(128) void attn_mma_kernel() {
    extern __shared__ char smem[];
    const uint32_t sb = s2u(smem);
    const int bh = blockIdx.y;
    const int b = bh >> 4;
    const int h = bh & 15;
    const int q0 = blockIdx.x * 64;
    const int tid = threadIdx.x;
    const int lane = tid & 31;
    const int w = tid >> 5;

    const __half* Qg = g_Qh + ((size_t)(b * SEQ) + q0) * CH + h * HD;

    auto load_kv = [&](int stage, int kb) {
        const __half* Kg = g_Kh + ((size_t)(b * SEQ) + kb) * CH + h * HD;
        const __half* Vg = g_Vh + ((size_t)(b * SEQ) + kb) * CH + h * HD;
        uint32_t kbB = sb + (KV_OFF + stage * STAGE_H) * 2;
        uint32_t vbB = kbB + 64 * ATS * 2;
        #pragma unroll
        for (int i = 0; i < 8; i++) {
            int idx = tid + i * 128;
            int row = idx >> 4, ch = idx & 15;
            uint32_t d = (row * ATS + ch * 8) * 2;
            cpa16(kbB + d, Kg + (size_t)row * CH + ch * 8);
            cpa16(vbB + d, Vg + (size_t)row * CH + ch * 8);
        }
    };

    {
        #pragma unroll
        for (int i = 0; i < 8; i++) {
            int idx = tid + i * 128;
            int row = idx >> 4, ch = idx & 15;
            cpa16(sb + (row * ATS + ch * 8) * 2, Qg + (size_t)row * CH + ch * 8);
        }
    }

    int cur = next_act(-64, q0);
    load_kv(0, cur);
    asm volatile("cp.async.commit_group;" ::: "memory");
    int nxt = next_act(cur, q0);
    if (nxt < SEQ) load_kv(1, nxt);
    asm volatile("cp.async.commit_group;" ::: "memory");
    int nn = (nxt < SEQ) ? next_act(nxt, q0) : SEQ;

    float m0 = -1e30f, m1 = -1e30f;
    float l0p = 0.0f, l1p = 0.0f;
    // O accumulators kept as packed f32x2 pairs: [t][0]=cols(0,1) [t][1]=cols(2,3)
    unsigned long long oacc[16][2];
    #pragma unroll
    for (int t = 0; t < 16; t++) { oacc[t][0] = 0ull; oacc[t][1] = 0ull; }

    int stage = 0;
    #pragma unroll 1
    while (cur < SEQ) {
        asm volatile("cp.async.wait_group 1;" ::: "memory");
        __syncthreads();

        uint32_t kbB = sb + (KV_OFF + stage * STAGE_H) * 2;
        uint32_t vbB = kbB + 64 * ATS * 2;

        float sacc[8][4];
        #pragma unroll
        for (int t = 0; t < 8; t++)
            #pragma unroll
            for (int r = 0; r < 4; r++) sacc[t][r] = 0.0f;

        #pragma unroll
        for (int ks = 0; ks < 8; ks++) {
            uint32_t aF[4];
            {
                int row = 16 * w + (lane & 15);
                uint32_t off = (row * ATS + ks * 16 + 8 * (lane >> 4)) * 2;
                ldm4(aF, sb + off);
            }
            #pragma unroll
            for (int jp = 0; jp < 4; jp++) {
                int row = 16 * jp + ((lane >> 4) << 3) + (lane & 7);
                uint32_t off = (row * ATS + ks * 16 + 8 * ((lane >> 3) & 1)) * 2;
                uint32_t r[4];
                ldm4(r, kbB + off);
                mma16(sacc[2 * jp],     aF, r);
                mma16(sacc[2 * jp + 1], aF, r + 2);
            }
        }

        bool needmask = (cur <= q0 + 63) && (cur + 63 >= q0 - (WIN - 1));
        if (needmask) {
            int i0 = q0 + 16 * w + (lane >> 2);
            int i1 = i0 + 8;
            #pragma unroll
            for (int t = 0; t < 8; t++) {
                int j0 = cur + 8 * t + 2 * (lane & 3);
                #pragma unroll
                for (int e = 0; e < 2; e++) {
                    int j = j0 + e;
                    bool msk0 = (j <= i0) && (j >= i0 - (WIN - 1));
                    bool msk1 = (j <= i1) && (j >= i1 - (WIN - 1));
                    if (msk0) sacc[t][e]     = -1e30f;
                    if (msk1) sacc[t][2 + e] = -1e30f;
                }
            }
        }

        float rmax0 = -1e30f, rmax1 = -1e30f;
        #pragma unroll
        for (int t = 0; t < 8; t++) {
            rmax0 = fmaxf(rmax0, fmaxf(sacc[t][0], sacc[t][1]));
            rmax1 = fmaxf(rmax1, fmaxf(sacc[t][2], sacc[t][3]));
        }
        rmax0 = fmaxf(rmax0, __shfl_xor_sync(0xffffffffu, rmax0, 1));
        rmax0 = fmaxf(rmax0, __shfl_xor_sync(0xffffffffu, rmax0, 2));
        rmax1 = fmaxf(rmax1, __shfl_xor_sync(0xffffffffu, rmax1, 1));
        rmax1 = fmaxf(rmax1, __shfl_xor_sync(0xffffffffu, rmax1, 2));
        float mn0 = fmaxf(m0, rmax0), mn1 = fmaxf(m1, rmax1);
        float cr0 = ex2(m0 - mn0), cr1 = ex2(m1 - mn1);

        // exp + packed pairwise sums
        unsigned long long ps0p = 0ull, ps1p = 0ull;
        #pragma unroll
        for (int t = 0; t < 8; t++) {
            sacc[t][0] = ex2(sacc[t][0] - mn0);
            sacc[t][1] = ex2(sacc[t][1] - mn0);
            sacc[t][2] = ex2(sacc[t][2] - mn1);
            sacc[t][3] = ex2(sacc[t][3] - mn1);
            ps0p = add2p(ps0p, pk2(sacc[t][0], sacc[t][1]));
            ps1p = add2p(ps1p, pk2(sacc[t][2], sacc[t][3]));
        }
        float pa, pb, ps0, ps1;
        upk2(ps0p, pa, pb);  ps0 = pa + pb;
        upk2(ps1p, pa, pb);  ps1 = pa + pb;

        l0p = l0p * cr0 + ps0;  m0 = mn0;
        l1p = l1p * cr1 + ps1;  m1 = mn1;

        // packed O rescale (cols 0,1 by cr0; cols 2,3 by cr1)
        unsigned long long c0p = pk2(cr0, cr0), c1p = pk2(cr1, cr1);
        #pragma unroll
        for (int t = 0; t < 16; t++) {
            oacc[t][0] = mul2p(oacc[t][0], c0p);
            oacc[t][1] = mul2p(oacc[t][1], c1p);
        }

        uint32_t aP[4][4];
        #pragma unroll
        for (int k2 = 0; k2 < 4; k2++) {
            aP[k2][0] = h2pack(sacc[2 * k2][0],     sacc[2 * k2][1]);
            aP[k2][1] = h2pack(sacc[2 * k2][2],     sacc[2 * k2][3]);
            aP[k2][2] = h2pack(sacc[2 * k2 + 1][0], sacc[2 * k2 + 1][1]);
            aP[k2][3] = h2pack(sacc[2 * k2 + 1][2], sacc[2 * k2 + 1][3]);
        }

        #pragma unroll
        for (int k2 = 0; k2 < 4; k2++) {
            #pragma unroll
            for (int dt = 0; dt < 8; dt++) {
                int row = 16 * k2 + ((lane >> 3) & 1) * 8 + (lane & 7);
                uint32_t off = (row * ATS + dt * 16 + ((lane >> 4) << 3)) * 2;
                uint32_t r[4];
                ldm4t(r, vbB + off);
                // unpack accumulators for mma, repack after
                float d0[4], d1[4];
                upk2(oacc[2 * dt][0],     d0[0], d0[1]);
                upk2(oacc[2 * dt][1],     d0[2], d0[3]);
                upk2(oacc[2 * dt + 1][0], d1[0], d1[1]);
                upk2(oacc[2 * dt + 1][1], d1[2], d1[3]);
                mma16(d0, aP[k2], r);
                mma16(d1, aP[k2], r + 2);
                oacc[2 * dt][0]     = pk2(d0[0], d0[1]);
                oacc[2 * dt][1]     = pk2(d0[2], d0[3]);
                oacc[2 * dt + 1][0] = pk2(d1[0], d1[1]);
                oacc[2 * dt + 1][1] = pk2(d1[2], d1[3]);
            }
        }

        __syncthreads();
        if (nn < SEQ) load_kv(stage, nn);
        asm volatile("cp.async.commit_group;" ::: "memory");
        cur = nxt;  nxt = nn;
        nn = (nn < SEQ) ? next_act(nn, q0) : SEQ;
        stage ^= 1;
    }

    float l0 = l0p, l1 = l1p;
    l0 += __shfl_xor_sync(0xffffffffu, l0, 1);
    l0 += __shfl_xor_sync(0xffffffffu, l0, 2);
    l1 += __shfl_xor_sync(0xffffffffu, l1, 1);
    l1 += __shfl_xor_sync(0xffffffffu, l1, 2);

    float il0 = 1.0f / l0, il1 = 1.0f / l1;
    int r0 = q0 + 16 * w + (lane >> 2);
    __half* Og = g_Ah + (size_t)(b * SEQ) * CH + h * HD;
    #pragma unroll
    for (int t = 0; t < 16; t++) {
        int c = 8 * t + 2 * (lane & 3);
        float a0, a1, a2, a3;
        upk2(oacc[t][0], a0, a1);
        upk2(oacc[t][1], a2, a3);
        __half2 h0 = __floats2half2_rn(a0 * il0, a1 * il0);
        __half2 h1 = __floats2half2_rn(a2 * il1, a3 * il1);
        *(__half2*)&Og[(size_t)r0 * CH + c] = h0;
        *(__half2*)&Og[(size_t)(r0 + 8) * CH + c] = h1;
    }
}

// ---------------- launch ----------------------------------------------------
extern "C" void kernel_launch(void* const* d_in, const int* in_sizes, int n_in,
                              void* d_out, int out_size) {
    const float* x  = (const float*)d_in[0];
    const float* Wq = (const float*)d_in[1];
    const float* Wk = (const float*)d_in[2];
    const float* Wv = (const float*)d_in[3];
    const float* Wo = (const float*)d_in[4];
    float* out = (float*)d_out;

    __half *Xh, *Wh, *Ahp;
    cudaGetSymbolAddress((void**)&Xh, g_Xh);
    cudaGetSymbolAddress((void**)&Wh, g_Wh);
    cudaGetSymbolAddress((void**)&Ahp, g_Ah);
    __half* Wh3 = Wh + 3 * (size_t)CH * CH;

    static bool attr_set = false;
    if (!attr_set) {
        cudaFuncSetAttribute(gemm_h<0>,
                             cudaFuncAttributeMaxDynamicSharedMemorySize,
                             GEMM_SMEM);
        cudaFuncSetAttribute(gemm_h<1>,
                             cudaFuncAttributeMaxDynamicSharedMemorySize,
                             GEMM_SMEM);
        cudaFuncSetAttribute(attn_mma_kernel,
                             cudaFuncAttributeMaxDynamicSharedMemorySize,
                             ATT_SMEM);
        attr_set = true;
    }

    prep_all<<<25088, 256>>>((const float4*)x, Wq, Wk, Wv, Wo);

    dim3 gq(CH / 128, MROWS / 128, 3);
    gemm_h<1><<<gq, 256, GEMM_SMEM>>>(Xh, Wh, nullptr);

    attn_mma_kernel<<<dim3(SEQ / 64, BATCH * NH), 128, ATT_SMEM>>>();

    dim3 gg(CH / 128, MROWS / 128, 1);
    gemm_h<0><<<gg, 256, GEMM_SMEM>>>(Ahp, Wh3, out);
}